// round 6
// baseline (speedup 1.0000x reference)
#include <cuda_runtime.h>
#include <cuda_fp16.h>
#include <math.h>
#include <stdint.h>

#define B_  32
#define S_  512
#define D_  9
#define E_  256
#define F_  1024
#define L_  4
#define C_  10
#define H_  8
#define HD_ 32
#define M_  (B_*S_)          // 16384 rows
#define KV_LD 512

// ---------------- scratch (static __device__, no allocs) ----------------
__device__ float g_x [M_*E_];         // activations fp32 (residual master)

// fp16 operand buffers
__device__ __half gx_h[M_*E_];        // x fp16
__device__ __half gk_h[M_*KV_LD];     // k(0..255), v->o(256..511) fp16
__device__ __half gh_h[M_*F_];        // ffn hidden fp16
__device__ __half wq_h[L_*3*E_*E_];
__device__ __half wo_h[L_*E_*E_];
__device__ __half w1_h[L_*F_*E_];
__device__ __half w2_h[L_*E_*F_];

// ================= PTX helpers (target-portable) =================
__device__ __forceinline__ uint32_t smem_u32(const void* p) {
    uint32_t a;
    asm("{ .reg .u64 t; cvta.to.shared.u64 t, %1; cvt.u32.u64 %0, t; }" : "=r"(a) : "l"(p));
    return a;
}
__device__ __forceinline__ void cp16(uint32_t dst, const void* src) {
    asm volatile("cp.async.cg.shared.global [%0], [%1], 16;\n" :: "r"(dst), "l"(src));
}
__device__ __forceinline__ void ldsm4(uint32_t* r, uint32_t addr) {
    asm volatile("ldmatrix.sync.aligned.m8n8.x4.shared.b16 {%0,%1,%2,%3}, [%4];"
        : "=r"(r[0]), "=r"(r[1]), "=r"(r[2]), "=r"(r[3]) : "r"(addr));
}
__device__ __forceinline__ void mma16816(float* d, const uint32_t* a, const uint32_t* b) {
    asm volatile("mma.sync.aligned.m16n8k16.row.col.f32.f16.f16.f32 "
        "{%0,%1,%2,%3}, {%4,%5,%6,%7}, {%8,%9}, {%0,%1,%2,%3};"
        : "+f"(d[0]), "+f"(d[1]), "+f"(d[2]), "+f"(d[3])
        : "r"(a[0]), "r"(a[1]), "r"(a[2]), "r"(a[3]), "r"(b[0]), "r"(b[1]));
}

// ================= GEMM: BM=128, BN=256, BK=64, 512 threads =================
// warp grid 2x8, warp tile 64x32, 3-stage cp.async pipeline.
// mode 0: write fp16 out; mode 1: relu + fp16 out;
// mode 2: fused bias + residual(g_x) + LayerNorm -> g_x fp32 + gx_h fp16 (requires N==256, bn==0)
#define STAGES 3
#define STAGE_BYTES 49152          // A 16K | B 32K
#define SMEM_RED (STAGES*STAGE_BYTES)
#define SMEM_REQ (SMEM_RED + 1024 + 1024)

__global__ __launch_bounds__(512, 1)
void gemm_mma(const __half* __restrict__ Ah, int lda,
              const __half* __restrict__ Bh,
              const float* __restrict__ bias,
              __half* __restrict__ outH,
              int N, int K, int mode,
              const float* __restrict__ lng, const float* __restrict__ lnb)
{
    extern __shared__ char dsm[];
    const uint32_t base = (smem_u32(dsm) + 1023u) & ~1023u;
    float* red = (float*)(dsm + (base - smem_u32(dsm)) + SMEM_RED);  // 128*2 floats
    const int tid = threadIdx.x;
    const int lane = tid & 31, wid = tid >> 5;
    const int bm = blockIdx.y * 128, bn = blockIdx.x * 256;
    const int wm = wid >> 3, wn = wid & 7;

    const size_t lda2 = (size_t)lda * 2, ldb2 = (size_t)K * 2;
    const char* gAh = (const char*)Ah + (size_t)bm * lda2;
    const char* gBh = (const char*)Bh + (size_t)bn * ldb2;

    const int cc  = tid & 7;       // 16B chunk within 128B row
    const int rr0 = tid >> 3;      // 0..63

    auto load_stage = [&](int kt, int s) {
        uint32_t st = base + (uint32_t)s * STAGE_BYTES;
        size_t gk = (size_t)kt * 128 + (size_t)cc * 16;
        #pragma unroll
        for (int j = 0; j < 2; j++) {          // A: 128 rows
            int r = rr0 + j * 64;
            uint32_t d = (uint32_t)(r * 128 + ((cc ^ (r & 7)) << 4));
            cp16(st + d, gAh + (size_t)r * lda2 + gk);
        }
        #pragma unroll
        for (int j = 0; j < 4; j++) {          // B: 256 rows
            int r = rr0 + j * 64;
            uint32_t d = (uint32_t)(r * 128 + ((cc ^ (r & 7)) << 4));
            cp16(st + 16384 + d, gBh + (size_t)r * ldb2 + gk);
        }
        asm volatile("cp.async.commit_group;\n" ::: "memory");
    };

    // ldmatrix lane geometry
    const int q = lane >> 3, r8 = lane & 7;
    int mRow[4], mSel[4];
    #pragma unroll
    for (int mt = 0; mt < 4; mt++) {
        int m = wm * 64 + mt * 16 + r8 + (q & 1) * 8;
        mRow[mt] = m * 128; mSel[mt] = m & 7;
    }
    const int aKH = q >> 1;
    int nRow[2], nSel[2];
    #pragma unroll
    for (int ng = 0; ng < 2; ng++) {
        int n = wn * 32 + ng * 16 + r8 + (q >> 1) * 8;
        nRow[ng] = n * 128; nSel[ng] = n & 7;
    }
    const int bKH = q & 1;

    float acc[4][4][4];
    #pragma unroll
    for (int a = 0; a < 4; a++)
        #pragma unroll
        for (int b = 0; b < 4; b++)
            #pragma unroll
            for (int c = 0; c < 4; c++) acc[a][b][c] = 0.f;

    const int nkt = K >> 6;
    load_stage(0, 0);
    if (nkt > 1) load_stage(1, 1);

    for (int kt = 0; kt < nkt; kt++) {
        if (kt + 2 < nkt) load_stage(kt + 2, (kt + 2) % STAGES);
        else asm volatile("cp.async.commit_group;\n" ::: "memory");
        asm volatile("cp.async.wait_group 2;\n" ::: "memory");
        __syncthreads();

        const uint32_t sb = base + (uint32_t)(kt % STAGES) * STAGE_BYTES;
        #pragma unroll
        for (int ks = 0; ks < 4; ks++) {
            uint32_t ah[4][4], bh[2][4];
            #pragma unroll
            for (int mt = 0; mt < 4; mt++) {
                uint32_t off = (uint32_t)(mRow[mt] + (((ks * 2 + aKH) ^ mSel[mt]) << 4));
                ldsm4(ah[mt], sb + off);
            }
            #pragma unroll
            for (int ng = 0; ng < 2; ng++) {
                uint32_t off = (uint32_t)(nRow[ng] + (((ks * 2 + bKH) ^ nSel[ng]) << 4));
                ldsm4(bh[ng], sb + 16384 + off);
            }
            #pragma unroll
            for (int mt = 0; mt < 4; mt++)
                #pragma unroll
                for (int nt = 0; nt < 4; nt++)
                    mma16816(acc[mt][nt], ah[mt], &bh[nt >> 1][(nt & 1) * 2]);
        }
        __syncthreads();
    }

    const int mE = lane >> 2;
    const int nE = (lane & 3) << 1;

    if (mode != 2) {
        // ---- plain epilogue: bias (+relu) -> fp16 out ----
        #pragma unroll
        for (int mt = 0; mt < 4; mt++) {
            #pragma unroll
            for (int nt = 0; nt < 4; nt++) {
                int m0 = bm + wm * 64 + mt * 16 + mE;
                int n0 = bn + wn * 32 + nt * 8 + nE;
                float b0v = bias[n0], b1v = bias[n0 + 1];
                float v00 = acc[mt][nt][0] + b0v;
                float v01 = acc[mt][nt][1] + b1v;
                float v10 = acc[mt][nt][2] + b0v;
                float v11 = acc[mt][nt][3] + b1v;
                if (mode == 1) {
                    v00 = fmaxf(v00, 0.f); v01 = fmaxf(v01, 0.f);
                    v10 = fmaxf(v10, 0.f); v11 = fmaxf(v11, 0.f);
                }
                size_t i0 = (size_t)m0 * N + n0;
                size_t i1 = (size_t)(m0 + 8) * N + n0;
                *(__half2*)(outH + i0) = __halves2half2(__float2half(v00), __float2half(v01));
                *(__half2*)(outH + i1) = __halves2half2(__float2half(v10), __float2half(v11));
            }
        }
        return;
    }

    // ---- fused LN epilogue (N==256, bn==0) ----
    // v = acc + bias + residual(g_x);  then rowwise LN -> g_x, gx_h
    if (tid < 256) { red[tid] = 0.f; }
    __syncthreads();

    #pragma unroll
    for (int mt = 0; mt < 4; mt++) {
        float s0 = 0.f, q0 = 0.f, s1 = 0.f, q1 = 0.f;
        #pragma unroll
        for (int nt = 0; nt < 4; nt++) {
            int m0 = bm + wm * 64 + mt * 16 + mE;
            int n0 = wn * 32 + nt * 8 + nE;
            float b0v = bias[n0], b1v = bias[n0 + 1];
            float2 r0 = *(const float2*)(g_x + (size_t)m0 * 256 + n0);
            float2 r1 = *(const float2*)(g_x + (size_t)(m0 + 8) * 256 + n0);
            float v00 = acc[mt][nt][0] + b0v + r0.x;
            float v01 = acc[mt][nt][1] + b1v + r0.y;
            float v10 = acc[mt][nt][2] + b0v + r1.x;
            float v11 = acc[mt][nt][3] + b1v + r1.y;
            acc[mt][nt][0] = v00; acc[mt][nt][1] = v01;
            acc[mt][nt][2] = v10; acc[mt][nt][3] = v11;
            s0 += v00 + v01; q0 += v00*v00 + v01*v01;
            s1 += v10 + v11; q1 += v10*v10 + v11*v11;
        }
        // reduce over the 4 lanes sharing a row (lane&3)
        #pragma unroll
        for (int o = 1; o <= 2; o <<= 1) {
            s0 += __shfl_xor_sync(0xffffffffu, s0, o);
            q0 += __shfl_xor_sync(0xffffffffu, q0, o);
            s1 += __shfl_xor_sync(0xffffffffu, s1, o);
            q1 += __shfl_xor_sync(0xffffffffu, q1, o);
        }
        if ((lane & 3) == 0) {
            int lr = wm * 64 + mt * 16 + mE;
            atomicAdd(&red[lr * 2],      s0);
            atomicAdd(&red[lr * 2 + 1],  q0);
            atomicAdd(&red[(lr+8) * 2],     s1);
            atomicAdd(&red[(lr+8) * 2 + 1], q1);
        }
    }
    __syncthreads();

    #pragma unroll
    for (int mt = 0; mt < 4; mt++) {
        int lr = wm * 64 + mt * 16 + mE;
        int m0 = bm + lr;
        float mean0 = red[lr*2] * (1.0f/256.0f);
        float var0  = red[lr*2+1] * (1.0f/256.0f) - mean0*mean0;
        float inv0  = rsqrtf(var0 + 1e-5f);
        float mean1 = red[(lr+8)*2] * (1.0f/256.0f);
        float var1  = red[(lr+8)*2+1] * (1.0f/256.0f) - mean1*mean1;
        float inv1  = rsqrtf(var1 + 1e-5f);
        #pragma unroll
        for (int nt = 0; nt < 4; nt++) {
            int n0 = wn * 32 + nt * 8 + nE;
            float g0 = lng[n0], g1 = lng[n0+1];
            float be0 = lnb[n0], be1 = lnb[n0+1];
            float r00 = (acc[mt][nt][0] - mean0) * inv0 * g0 + be0;
            float r01 = (acc[mt][nt][1] - mean0) * inv0 * g1 + be1;
            float r10 = (acc[mt][nt][2] - mean1) * inv1 * g0 + be0;
            float r11 = (acc[mt][nt][3] - mean1) * inv1 * g1 + be1;
            size_t i0 = (size_t)m0 * 256 + n0;
            size_t i1 = (size_t)(m0 + 8) * 256 + n0;
            *(float2*)(g_x + i0) = make_float2(r00, r01);
            *(float2*)(g_x + i1) = make_float2(r10, r11);
            *(__half2*)(gx_h + i0) = __halves2half2(__float2half(r00), __float2half(r01));
            *(__half2*)(gx_h + i1) = __halves2half2(__float2half(r10), __float2half(r11));
        }
    }
}

// ---------------- weight -> fp16 ----------------
__global__ void split1_kernel(const float* __restrict__ src,
                              __half* __restrict__ h, int n) {
    int i = blockIdx.x * blockDim.x + threadIdx.x;
    int stride = gridDim.x * blockDim.x;
    for (; i < n; i += stride) h[i] = __float2half(src[i]);
}

// ---------------- reductions ----------------
__device__ __forceinline__ float warpSum(float v) {
    #pragma unroll
    for (int o = 16; o > 0; o >>= 1) v += __shfl_xor_sync(0xffffffffu, v, o);
    return v;
}
__device__ __forceinline__ float warpMax(float v) {
    #pragma unroll
    for (int o = 16; o > 0; o >>= 1) v = fmaxf(v, __shfl_xor_sync(0xffffffffu, v, o));
    return v;
}
__device__ float blockSum(float v, float* red) {
    int lane = threadIdx.x & 31, wid = threadIdx.x >> 5;
    v = warpSum(v);
    if (lane == 0) red[wid] = v;
    __syncthreads();
    if (wid == 0) {
        float x = (lane < 8) ? red[lane] : 0.f;
        x = warpSum(x);
        if (lane == 0) red[0] = x;
    }
    __syncthreads();
    float r = red[0];
    __syncthreads();
    return r;
}
__device__ float blockMax(float v, float* red) {
    int lane = threadIdx.x & 31, wid = threadIdx.x >> 5;
    v = warpMax(v);
    if (lane == 0) red[wid] = v;
    __syncthreads();
    if (wid == 0) {
        float x = (lane < 8) ? red[lane] : -1e30f;
        x = warpMax(x);
        if (lane == 0) red[0] = x;
    }
    __syncthreads();
    float r = red[0];
    __syncthreads();
    return r;
}

// ---------------- embed + posenc (fp32 + fp16) ----------------
__global__ void embed_kernel(const float* __restrict__ src,
                             const float* __restrict__ embW,
                             const float* __restrict__ embb) {
    int m = blockIdx.x;
    int e = threadIdx.x;
    __shared__ float sv[D_];
    if (e < D_) sv[e] = src[m*D_ + e];
    __syncthreads();
    float acc = 0.f;
    #pragma unroll
    for (int d = 0; d < D_; d++) acc += sv[d] * embW[e*D_ + d];
    acc = (acc + embb[e]) * 16.0f;
    int s  = m & (S_-1);
    int j2 = (e >> 1) * 2;
    const float c = -9.210340371976184f / (float)E_;
    float ang = (float)s * expf((float)j2 * c);
    float pe  = (e & 1) ? cosf(ang) : sinf(ang);
    float val = acc + pe;
    size_t idx = (size_t)m*E_ + e;
    g_x[idx] = val;
    gx_h[idx] = __float2half(val);
}

// ---------------- sparse attention (last query row only) ----------------
__global__ __launch_bounds__(256)
void attn_kernel(float* __restrict__ out_attn, int l,
                 const float* __restrict__ Wq, const float* __restrict__ bq) {
    int b = blockIdx.x;
    int t = threadIdx.x;
    __shared__ float sc[S_];
    __shared__ float arow[S_];
    __shared__ float xlast[E_];
    __shared__ float q_sh[E_];
    __shared__ float red[32];
    __shared__ float opart[8*HD_];
    arow[t] = 0.f; arow[t+256] = 0.f;
    const float scale = 0.17677669529663687f;
    const __half* kv = gk_h;
    size_t rowLast = (size_t)(b*S_ + (S_-1)) * KV_LD;

    xlast[t] = g_x[(size_t)(b*S_ + (S_-1))*E_ + t];
    __syncthreads();
    {
        float a = 0.f;
        const float* wr = Wq + (size_t)t * E_;
        #pragma unroll 8
        for (int i = 0; i < E_; i++) a += xlast[i] * wr[i];
        q_sh[t] = a + bq[t];
    }
    __syncthreads();

    for (int h = 0; h < H_; h++) {
        const float* qv = q_sh + h*HD_;
        float s1, s2;
        {
            const __half* kr = kv + (size_t)(b*S_ + t)*KV_LD + h*HD_;
            float a = 0.f;
            #pragma unroll
            for (int d = 0; d < HD_; d++) a += qv[d]*__half2float(kr[d]);
            s1 = a * scale;
            int k2 = t + 256;
            if (k2 != S_-1) {
                const __half* kr2 = kv + (size_t)(b*S_ + k2)*KV_LD + h*HD_;
                float a2 = 0.f;
                #pragma unroll
                for (int d = 0; d < HD_; d++) a2 += qv[d]*__half2float(kr2[d]);
                s2 = a2 * scale;
            } else s2 = -1e30f;
        }
        float mx  = blockMax(fmaxf(s1, s2), red);
        float e1  = expf(s1 - mx);
        float e2  = (t + 256 == S_-1) ? 0.f : expf(s2 - mx);
        float sum = blockSum(e1 + e2, red);
        float inv = 1.0f / sum;
        float a1 = e1*inv, a2 = e2*inv;
        sc[t] = a1; sc[t+256] = a2;
        arow[t]     += a1 * 0.125f;
        arow[t+256] += a2 * 0.125f;
        __syncthreads();
        int g = t >> 5, d = t & 31;
        float oa = 0.f;
        for (int k = g; k < S_-1; k += 8)
            oa += sc[k] * __half2float(kv[(size_t)(b*S_ + k)*KV_LD + E_ + h*HD_ + d]);
        opart[g*HD_ + d] = oa;
        __syncthreads();
        if (t < HD_) {
            float o = 0.f;
            #pragma unroll
            for (int gg = 0; gg < 8; gg++) o += opart[gg*HD_ + t];
            gk_h[rowLast + E_ + h*HD_ + t] = __float2half(o);
        }
        __syncthreads();
    }
    size_t basei = ((size_t)(l*B_ + b)*S_ + (S_-1)) * S_;
    out_attn[basei + t]       = arow[t];
    out_attn[basei + t + 256] = arow[t+256];
}

// ---------------- decode head ----------------
__global__ __launch_bounds__(256)
void final_kernel(const float* __restrict__ decW, float* __restrict__ out) {
    int b = blockIdx.x, e = threadIdx.x;
    __shared__ float xs[E_];
    __shared__ float lg[C_];
    __shared__ float lse_s;
    float acc = 0.f;
    for (int s = 0; s < S_; s++)
        acc += fmaxf(g_x[((size_t)b*S_ + s)*E_ + e], 0.f);
    xs[e] = acc * (1.0f/S_);
    __syncthreads();
    if (e < C_) {
        float a = 0.f;
        for (int i = 0; i < E_; i++) a += xs[i]*decW[e*E_ + i];
        lg[e] = a;
    }
    __syncthreads();
    if (e == 0) {
        float m = -1e30f;
        for (int c = 0; c < C_; c++) m = fmaxf(m, lg[c]);
        float s = 0.f;
        for (int c = 0; c < C_; c++) s += expf(lg[c]-m);
        lse_s = m + logf(s);
    }
    __syncthreads();
    if (e < C_) out[b*C_ + e] = lg[e] - lse_s;
}

// ---------------- attns constant fill ----------------
__global__ void fill_zero(float4* __restrict__ p, int n4) {
    int i = blockIdx.x*blockDim.x + threadIdx.x;
    int stride = gridDim.x*blockDim.x;
    float4 z = make_float4(0.f,0.f,0.f,0.f);
    for (; i < n4; i += stride) p[i] = z;
}
__global__ void fill_ones(float* __restrict__ p) {
    int i = blockIdx.x*blockDim.x + threadIdx.x;
    if (i >= L_*B_*(S_-1)) return;
    int q  = i % (S_-1);
    int lb = i / (S_-1);
    p[((size_t)lb*S_ + q)*S_ + q] = 1.0f;
}

// ---------------- host ----------------
extern "C" void kernel_launch(void* const* d_in, const int* in_sizes, int n_in,
                              void* d_out, int out_size) {
    const float* src   = (const float*)d_in[0];
    const float* embW  = (const float*)d_in[1];
    const float* embb  = (const float*)d_in[2];
    const float* Wqkv  = (const float*)d_in[3];
    const float* bqkv  = (const float*)d_in[4];
    const float* Wo    = (const float*)d_in[5];
    const float* bo    = (const float*)d_in[6];
    const float* ln1g  = (const float*)d_in[7];
    const float* ln1b  = (const float*)d_in[8];
    const float* ln2g  = (const float*)d_in[9];
    const float* ln2b  = (const float*)d_in[10];
    const float* W1    = (const float*)d_in[11];
    const float* b1    = (const float*)d_in[12];
    const float* W2    = (const float*)d_in[13];
    const float* b2    = (const float*)d_in[14];
    const float* decW  = (const float*)d_in[15];
    float* out = (float*)d_out;
    float* out_attn = out + B_*C_;

    __half *xh, *kh, *hh;
    __half *wqh, *woh, *w1h, *w2h;
    cudaGetSymbolAddress((void**)&xh, gx_h);
    cudaGetSymbolAddress((void**)&kh, gk_h);
    cudaGetSymbolAddress((void**)&hh, gh_h);
    cudaGetSymbolAddress((void**)&wqh, wq_h);
    cudaGetSymbolAddress((void**)&woh, wo_h);
    cudaGetSymbolAddress((void**)&w1h, w1_h);
    cudaGetSymbolAddress((void**)&w2h, w2_h);

    cudaFuncSetAttribute(gemm_mma, cudaFuncAttributeMaxDynamicSharedMemorySize, SMEM_REQ);

    split1_kernel<<<1024, 256>>>(Wqkv, wqh, L_*3*E_*E_);
    split1_kernel<<<512,  256>>>(Wo,   woh, L_*E_*E_);
    split1_kernel<<<1024, 256>>>(W1,   w1h, L_*F_*E_);
    split1_kernel<<<1024, 256>>>(W2,   w2h, L_*E_*F_);

    embed_kernel<<<M_, 256>>>(src, embW, embb);

    int n4 = (L_*B_*S_*S_) / 4;
    fill_zero<<<4096, 256>>>((float4*)out_attn, n4);
    fill_ones<<<(L_*B_*(S_-1) + 255)/256, 256>>>(out_attn);

    for (int l = 0; l < L_; l++) {
        const size_t wq_off = (size_t)l*3*E_*E_;
        // kv = x @ [Wk;Wv]^T + b   [16384,512] -> fp16
        gemm_mma<<<dim3(2, 128), 512, SMEM_REQ>>>(
            xh, E_, wqh + wq_off + (size_t)E_*E_,
            bqkv + l*3*E_ + E_, kh, KV_LD, E_, 0, (const float*)0, (const float*)0);
        // sparse attention: q_last in-kernel; patches v last row fp16
        attn_kernel<<<B_, 256>>>(out_attn, l, Wqkv + wq_off, bqkv + l*3*E_);
        // x = LN1(x + o @ Wo^T + bo)  -- fused
        gemm_mma<<<dim3(1, 128), 512, SMEM_REQ>>>(
            kh + E_, KV_LD, woh + (size_t)l*E_*E_,
            bo + l*E_, (__half*)0, E_, E_, 2, ln1g + l*E_, ln1b + l*E_);
        // h = relu(x @ W1^T + b1) -> fp16
        gemm_mma<<<dim3(4, 128), 512, SMEM_REQ>>>(
            xh, E_, w1h + (size_t)l*F_*E_,
            b1 + l*F_, hh, F_, E_, 1, (const float*)0, (const float*)0);
        // x = LN2(x + h @ W2^T + b2)  -- fused
        gemm_mma<<<dim3(1, 128), 512, SMEM_REQ>>>(
            hh, F_, w2h + (size_t)l*E_*F_,
            b2 + l*E_, (__half*)0, E_, F_, 2, ln2g + l*E_, ln2b + l*E_);
    }

    final_kernel<<<B_, 256>>>(decW, out);
}